// round 14
// baseline (speedup 1.0000x reference)
#include <cuda_runtime.h>
#include <cstdint>
#include <math_constants.h>

#define NND 100000
#define NE  3200000
#define NG  128
#define NH  32
#define FULL 0xffffffffu

// ---------------- device scratch (allocation-free) ----------------
__device__ __align__(16) float g_agg1[2 * NND];          // 0.8 MB
__device__ __align__(16) float g_t   [2 * NND];          // 0.8 MB
__device__ __align__(16) int   g_P   [2 * NND];          // 0.8 MB   packed (j<<25)|A
__device__ __align__(16) int   g_bkt [2LL * NND * 33];   // 26.4 MB  packed count/sum
__device__ __align__(16) float g_pool[NG * NH];          // 16 KB (signed: g1 +, g2 -)
__device__ float g_th[NH];     // sorted thresholds
__device__ int   g_rank[NH];   // rank of threshold k
__device__ unsigned int g_ctr; // node_out completion counter (across all 3 launches)

// ---------------- int64 vs int32 index detection ----------------
__device__ __forceinline__ bool detect_int64(const void* p, long long nelem,
                                             unsigned long long maxval) {
    const long long* q = (const long long*)p;
    long long a = q[nelem / 2 - 1];
    long long b = q[nelem / 2 - 2];
    return ((unsigned long long)a < maxval) && ((unsigned long long)b < maxval);
}

// Load 4 consecutive edges (e % 4 == 0) with wide loads.
__device__ __forceinline__ void load_edge4(const void* ep, bool is64, long long e,
                                           int (&src)[4], int (&dst)[4]) {
    if (is64) {
        const longlong2* q = (const longlong2*)ep;
        longlong2 s0 = q[e >> 1], s1 = q[(e >> 1) + 1];
        longlong2 d0 = q[((long long)NE + e) >> 1], d1 = q[(((long long)NE + e) >> 1) + 1];
        src[0] = (int)s0.x; src[1] = (int)s0.y; src[2] = (int)s1.x; src[3] = (int)s1.y;
        dst[0] = (int)d0.x; dst[1] = (int)d0.y; dst[2] = (int)d1.x; dst[3] = (int)d1.y;
    } else {
        const int* qi = (const int*)ep;
        int4 s = ((const int4*)qi)[e >> 2];
        int4 d = ((const int4*)(qi + NE))[e >> 2];
        src[0] = s.x; src[1] = s.y; src[2] = s.z; src[3] = s.w;
        dst[0] = d.x; dst[1] = d.y; dst[2] = d.z; dst[3] = d.w;
    }
}

// ---------------- kernels ----------------

// Tiny head zero: agg1 (both) + pool + ctr + threshold sort.
__global__ void zeroA_kernel(const float* __restrict__ W1,
                             const float* __restrict__ b1) {
    int i = blockIdx.x * blockDim.x + threadIdx.x;
    float4 zf = make_float4(0.f, 0.f, 0.f, 0.f);
    if (i < 2 * NND / 4)  ((float4*)g_agg1)[i] = zf;
    if (i < NG * NH / 4)  ((float4*)g_pool)[i] = zf;

    if (blockIdx.x == 0) {
        if (threadIdx.x == 32) g_ctr = 0u;
        if (threadIdx.x < 32) {
            int lane = threadIdx.x;
            float w = W1[lane], b = b1[lane];
            float th = (w != 0.f) ? (-b / w) : CUDART_INF_F;
            int r = 0;
#pragma unroll
            for (int k = 0; k < NH; k++) {
                float o = __shfl_sync(FULL, th, k);
                r += (o < th) || (o == th && k < lane);
            }
            g_th[r] = th;
            g_rank[lane] = r;
        }
    }
}

// Per-graph bucket zero (13.2 MB), coalesced int4 stores.
__global__ void __launch_bounds__(256) zbkt_kernel(int g) {
    const long long NB4 = (long long)NND * 33 / 4;   // 825000
    long long i = (long long)blockIdx.x * blockDim.x + threadIdx.x;
    if (i < NB4)
        ((int4*)(g_bkt + (long long)g * NND * 33))[i] = make_int4(0, 0, 0, 0);
}

// Stage 1 (per graph): agg1[dst] += x[src]. ILP-4.
__global__ void __launch_bounds__(256) edge1_kernel(
        const float* __restrict__ x, const void* __restrict__ ep, int g) {
    long long tid = (long long)blockIdx.x * blockDim.x + threadIdx.x;
    const long long NT = (long long)NE / 4;
    if (tid >= NT) return;
    bool is64 = detect_int64(ep, 2LL * NE, (unsigned long long)NND);
    long long e = tid * 4;

    int s[4], d[4];
    load_edge4(ep, is64, e, s, d);
    float xv[4];
#pragma unroll
    for (int u = 0; u < 4; u++) xv[u] = __ldg(&x[s[u]]);
    float* aggb = g_agg1 + g * NND;
#pragma unroll
    for (int u = 0; u < 4; u++) atomicAdd(&aggb[d[u]], xv[u]);
}

// (per graph) t = x + agg1; bucket j = #(sorted th <= t); pack P.
__global__ void node_t_kernel(const float* __restrict__ x, int g) {
    __shared__ float th_s[32 * 32];
    for (int i = threadIdx.x; i < 32 * 32; i += blockDim.x) th_s[i] = g_th[i >> 5];
    __syncthreads();

    int i = blockIdx.x * blockDim.x + threadIdx.x;
    if (i >= NND) return;
    float t = x[i] + g_agg1[g * NND + i];

    int lane = threadIdx.x & 31;
    int j = 0;
#pragma unroll
    for (int st = 16; st >= 1; st >>= 1) {
        int c = j + st;
        if (th_s[((c - 1) << 5) | lane] <= t) j = c;
    }
    if (j == 31 && th_s[(31 << 5) | lane] <= t) j = 32;

    int q = __float2int_rn(t * 1024.f);
    int A = (1 << 24) + (1 << 17) + q;
    g_t[g * NND + i] = t;
    g_P[g * NND + i] = (j << 25) | A;
}

// Stage 2 (per graph): one RED.32 per edge: bkt[dst*33 + j] += A. ILP-4.
__global__ void __launch_bounds__(256) edgeb_kernel(const void* __restrict__ ep, int g) {
    long long tid = (long long)blockIdx.x * blockDim.x + threadIdx.x;
    const long long NT = (long long)NE / 4;
    if (tid >= NT) return;
    bool is64 = detect_int64(ep, 2LL * NE, (unsigned long long)NND);
    long long e = tid * 4;

    int s[4], d[4];
    load_edge4(ep, is64, e, s, d);
    const int* Pb = g_P + g * NND;
    int P[4];
#pragma unroll
    for (int u = 0; u < 4; u++) P[u] = __ldg(&Pb[s[u]]);

    int* bktb = g_bkt + (long long)g * NND * 33;
#pragma unroll
    for (int u = 0; u < 4; u++) {
        int j = P[u] >> 25;
        int A = P[u] & 0x01FFFFFF;
        atomicAdd(&bktb[d[u] * 33 + j], A);
    }
}

// Stage 3 (per graph, warp range [w0, w0+nw)): decode buckets, layer2, pool.
// Warp per 4 nodes, 2-node interleaved chains, W2 in shared.
// Last completing block across ALL node_out launches writes |pool| to out.
__global__ void __launch_bounds__(256) node_out_kernel(
        const void* __restrict__ bp,
        const float* __restrict__ W1, const float* __restrict__ b1,
        const float* __restrict__ W2, const float* __restrict__ b2,
        int g, float sign, int w0, int nw,
        float* __restrict__ out, int totalBlocks) {
    __shared__ float W2s[NH][NH];
    for (int i = threadIdx.x; i < NH * NH; i += blockDim.x)
        W2s[i >> 5][i & 31] = W2[i];
    __syncthreads();

    const int CH = 4;
    const int chunks = NND / CH;  // 25000
    int lane = threadIdx.x & 31;
    int lw = (blockIdx.x * blockDim.x + threadIdx.x) >> 5;
    int warp = w0 + lw;
    bool active = (lw < nw) && (warp < chunks);
    int start = active ? warp * CH : 0;

    bool is64 = detect_int64(bp, (long long)NND, (unsigned long long)NG);
    float w1  = W1[lane];
    float bb1 = b1[lane];
    float bb2 = b2[lane];
    int   rnk = g_rank[lane];

    if (active) {
        const float* tb = g_t + g * NND;
        float poolacc = 0.f;
        int curg = -1;

        for (int n = start; n < start + CH; n += 2) {
            const int* bktA = &g_bkt[((long long)(g * NND + n)) * 33];
            int VA = bktA[1 + lane], VA0 = bktA[0];
            int VB = bktA[33 + 1 + lane], VB0 = bktA[33];
            float tA = tb[n], tBv = tb[n + 1];

            float ccA = (float)(VA >> 24);
            float ssA = (float)((VA & 0xFFFFFF) - ((VA >> 24) << 17)) * (1.f / 1024.f);
            float ccB = (float)(VB >> 24);
            float ssB = (float)((VB & 0xFFFFFF) - ((VB >> 24) << 17)) * (1.f / 1024.f);
#pragma unroll
            for (int off = 1; off < 32; off <<= 1) {   // interleaved suffix scans
                float a1 = __shfl_down_sync(FULL, ssA, off);
                float a2 = __shfl_down_sync(FULL, ccA, off);
                float b1_ = __shfl_down_sync(FULL, ssB, off);
                float b2_ = __shfl_down_sync(FULL, ccB, off);
                if (lane + off < 32) { ssA += a1; ccA += a2; ssB += b1_; ccB += b2_; }
            }
            float c0A = (float)(VA0 >> 24);
            float s0A = (float)((VA0 & 0xFFFFFF) - ((VA0 >> 24) << 17)) * (1.f / 1024.f);
            float c0B = (float)(VB0 >> 24);
            float s0B = (float)((VB0 & 0xFFFFFF) - ((VB0 >> 24) << 17)) * (1.f / 1024.f);
            float TSA = s0A + __shfl_sync(FULL, ssA, 0);
            float TCA = c0A + __shfl_sync(FULL, ccA, 0);
            float TSB = s0B + __shfl_sync(FULL, ssB, 0);
            float TCB = c0B + __shfl_sync(FULL, ccB, 0);
            float mSA = __shfl_sync(FULL, ssA, rnk);
            float mCA = __shfl_sync(FULL, ccA, rnk);
            float mSB = __shfl_sync(FULL, ssB, rnk);
            float mCB = __shfl_sync(FULL, ccB, rnk);

            float aggA, aggB;
            if (w1 > 0.f) {
                aggA = w1 * mSA + bb1 * mCA;
                aggB = w1 * mSB + bb1 * mCB;
            } else if (w1 < 0.f) {
                aggA = w1 * (TSA - mSA) + bb1 * (TCA - mCA);
                aggB = w1 * (TSB - mSB) + bb1 * (TCB - mCB);
            } else {
                aggA = fmaxf(bb1, 0.f) * TCA;
                aggB = fmaxf(bb1, 0.f) * TCB;
            }

            float vA = fmaxf(fmaf(tA,  w1, bb1), 0.f) + aggA;
            float vB = fmaxf(fmaf(tBv, w1, bb1), 0.f) + aggB;

            float accA = bb2, accA2 = 0.f, accB = bb2, accB2 = 0.f;
#pragma unroll
            for (int k = 0; k < 32; k += 2) {
                float w2a = W2s[k][lane], w2b = W2s[k + 1][lane];
                accA  = fmaf(__shfl_sync(FULL, vA, k),     w2a, accA);
                accA2 = fmaf(__shfl_sync(FULL, vA, k + 1), w2b, accA2);
                accB  = fmaf(__shfl_sync(FULL, vB, k),     w2a, accB);
                accB2 = fmaf(__shfl_sync(FULL, vB, k + 1), w2b, accB2);
            }
            float oA = fmaxf(accA + accA2, 0.f);
            float oB = fmaxf(accB + accB2, 0.f);

            int bgA = is64 ? (int)((const long long*)bp)[n]
                           : ((const int*)bp)[n];
            int bgB = is64 ? (int)((const long long*)bp)[n + 1]
                           : ((const int*)bp)[n + 1];
            if (bgA != curg) {
                if (curg >= 0) atomicAdd(&g_pool[curg * NH + lane], sign * poolacc);
                poolacc = 0.f;
                curg = bgA;
            }
            poolacc += oA;
            if (bgB != curg) {
                atomicAdd(&g_pool[curg * NH + lane], sign * poolacc);
                poolacc = 0.f;
                curg = bgB;
            }
            poolacc += oB;
        }
        if (curg >= 0) atomicAdd(&g_pool[curg * NH + lane], sign * poolacc);
    }

    // completion counter across all node_out launches; last block writes |pool|
    __shared__ unsigned int s_last;
    __threadfence();
    __syncthreads();
    if (threadIdx.x == 0) {
        unsigned int done = atomicAdd(&g_ctr, 1u);
        s_last = (done == (unsigned int)(totalBlocks - 1)) ? 1u : 0u;
    }
    __syncthreads();
    if (s_last) {
        for (int i = threadIdx.x; i < NG * NH; i += blockDim.x)
            out[i] = fabsf(g_pool[i]);
    }
}

// ---------------- launch: 2-stream staggered pipeline ----------------
// All cudaEventRecord calls precede their cudaStreamWaitEvent in ENQUEUE order
// (required under graph capture — the R13 failure).
extern "C" void kernel_launch(void* const* d_in, const int* in_sizes, int n_in,
                              void* d_out, int out_size) {
    const float* x1  = (const float*)d_in[0];
    const void*  ei1 = d_in[1];
    const void*  bt1 = d_in[2];
    const float* x2  = (const float*)d_in[3];
    const void*  ei2 = d_in[4];
    const void*  bt2 = d_in[5];
    const float* W1  = (const float*)d_in[6];
    const float* b1  = (const float*)d_in[7];
    const float* W2  = (const float*)d_in[8];
    const float* b2  = (const float*)d_in[9];
    float* out = (float*)d_out;

    static cudaStream_t s2 = nullptr;
    static cudaEvent_t ev0 = nullptr, evA = nullptr, evZ = nullptr,
                       evE1 = nullptr, ev2 = nullptr;
    if (!s2) {
        cudaStreamCreateWithFlags(&s2, cudaStreamNonBlocking);
        cudaEventCreateWithFlags(&ev0, cudaEventDisableTiming);
        cudaEventCreateWithFlags(&evA, cudaEventDisableTiming);
        cudaEventCreateWithFlags(&evZ, cudaEventDisableTiming);
        cudaEventCreateWithFlags(&evE1, cudaEventDisableTiming);
        cudaEventCreateWithFlags(&ev2, cudaEventDisableTiming);
    }

    const int EB = (int)(((long long)NE / 4 + 255) / 256);        // edge blocks / graph
    const int NB = (NND + 255) / 256;                             // node_t blocks / graph
    const int ZB = (int)(((long long)NND * 33 / 4 + 255) / 256);  // zbkt blocks / graph

    const int chunks = NND / 4;                      // 25000 warps per graph
    const int HALF   = chunks / 2;                   // 12500
    const int OB_FULL = (chunks * 32 + 255) / 256;   // 3125 blocks
    const int OB_HALF = (HALF * 32 + 255) / 256;     // 1563 blocks
    const int TOTAL_NO_BLOCKS = OB_FULL + 2 * OB_HALF;  // 6251

    // head on main: tiny zero + prep, fork marker
    zeroA_kernel<<<(2 * NND / 4 + 255) / 256, 256>>>(W1, b1);
    cudaEventRecord(ev0, 0);

    // main: zero both graphs' buckets (will overlap s2's edge1), record evZ NOW
    zbkt_kernel<<<ZB, 256>>>(0);
    zbkt_kernel<<<ZB, 256>>>(1);
    cudaEventRecord(evZ, 0);

    // s2: graph-2 chain
    cudaStreamWaitEvent(s2, ev0, 0);
    edge1_kernel<<<EB, 256, 0, s2>>>(x2, ei2, 1);
    cudaEventRecord(evA, s2);                    // g2 edge1 done
    node_t_kernel<<<NB, 256, 0, s2>>>(x2, 1);
    cudaStreamWaitEvent(s2, evZ, 0);             // buckets zeroed (recorded above)
    edgeb_kernel<<<EB, 256, 0, s2>>>(ei2, 1);
    node_out_kernel<<<OB_FULL, 256, 0, s2>>>(bt2, W1, b1, W2, b2, 1, -1.f,
                                             0, chunks, out, TOTAL_NO_BLOCKS);

    // main: g1 chain, staggered behind g2's edge1
    cudaStreamWaitEvent(0, evA, 0);
    edge1_kernel<<<EB, 256>>>(x1, ei1, 0);
    node_t_kernel<<<NB, 256>>>(x1, 0);
    edgeb_kernel<<<EB, 256>>>(ei1, 0);
    cudaEventRecord(evE1, 0);                    // g1 edgeb done

    // tail: split g1's node_out across both streams
    node_out_kernel<<<OB_HALF, 256>>>(bt1, W1, b1, W2, b2, 0, 1.f,
                                      0, HALF, out, TOTAL_NO_BLOCKS);
    cudaStreamWaitEvent(s2, evE1, 0);
    node_out_kernel<<<OB_HALF, 256, 0, s2>>>(bt1, W1, b1, W2, b2, 0, 1.f,
                                             HALF, chunks - HALF, out, TOTAL_NO_BLOCKS);
    cudaEventRecord(ev2, s2);

    // join
    cudaStreamWaitEvent(0, ev2, 0);
}

// round 15
// speedup vs baseline: 1.0902x; 1.0902x over previous
#include <cuda_runtime.h>
#include <cstdint>
#include <math_constants.h>

#define NND 100000
#define NE  3200000
#define NG  128
#define NH  32
#define FULL 0xffffffffu

// ---------------- device scratch (allocation-free) ----------------
__device__ __align__(16) float g_agg1[2 * NND];          // 0.8 MB
__device__ __align__(16) float g_t   [2 * NND];          // 0.8 MB
__device__ __align__(16) int   g_P   [2 * NND];          // 0.8 MB   packed (j<<25)|A
__device__ __align__(16) int   g_bkt [2LL * NND * 33];   // 26.4 MB  packed count/sum
__device__ __align__(16) float g_pool[NG * NH];          // 16 KB (signed: g1 +, g2 -)
__device__ float g_th[NH];     // sorted thresholds
__device__ int   g_rank[NH];   // rank of threshold k

// ---------------- int64 vs int32 index detection ----------------
__device__ __forceinline__ bool detect_int64(const void* p, long long nelem,
                                             unsigned long long maxval) {
    const long long* q = (const long long*)p;
    long long a = q[nelem / 2 - 1];
    long long b = q[nelem / 2 - 2];
    return ((unsigned long long)a < maxval) && ((unsigned long long)b < maxval);
}

// Load 4 consecutive edges (e % 4 == 0) with wide loads.
__device__ __forceinline__ void load_edge4(const void* ep, bool is64, long long e,
                                           int (&src)[4], int (&dst)[4]) {
    if (is64) {
        const longlong2* q = (const longlong2*)ep;
        longlong2 s0 = q[e >> 1], s1 = q[(e >> 1) + 1];
        longlong2 d0 = q[((long long)NE + e) >> 1], d1 = q[(((long long)NE + e) >> 1) + 1];
        src[0] = (int)s0.x; src[1] = (int)s0.y; src[2] = (int)s1.x; src[3] = (int)s1.y;
        dst[0] = (int)d0.x; dst[1] = (int)d0.y; dst[2] = (int)d1.x; dst[3] = (int)d1.y;
    } else {
        const int* qi = (const int*)ep;
        int4 s = ((const int4*)qi)[e >> 2];
        int4 d = ((const int4*)(qi + NE))[e >> 2];
        src[0] = s.x; src[1] = s.y; src[2] = s.z; src[3] = s.w;
        dst[0] = d.x; dst[1] = d.y; dst[2] = d.z; dst[3] = d.w;
    }
}

// ---------------- kernels ----------------

// Tiny head zero: agg1 (both) + pool + threshold sort.
__global__ void zeroA_kernel(const float* __restrict__ W1,
                             const float* __restrict__ b1) {
    int i = blockIdx.x * blockDim.x + threadIdx.x;
    float4 zf = make_float4(0.f, 0.f, 0.f, 0.f);
    if (i < 2 * NND / 4)  ((float4*)g_agg1)[i] = zf;
    if (i < NG * NH / 4)  ((float4*)g_pool)[i] = zf;

    if (blockIdx.x == 0 && threadIdx.x < 32) {
        int lane = threadIdx.x;
        float w = W1[lane], b = b1[lane];
        float th = (w != 0.f) ? (-b / w) : CUDART_INF_F;
        int r = 0;
#pragma unroll
        for (int k = 0; k < NH; k++) {
            float o = __shfl_sync(FULL, th, k);
            r += (o < th) || (o == th && k < lane);
        }
        g_th[r] = th;
        g_rank[lane] = r;
    }
}

// Per-graph bucket zero (13.2 MB), coalesced int4 stores.
__global__ void __launch_bounds__(256) zbkt_kernel(int g) {
    const long long NB4 = (long long)NND * 33 / 4;   // 825000
    long long i = (long long)blockIdx.x * blockDim.x + threadIdx.x;
    if (i < NB4)
        ((int4*)(g_bkt + (long long)g * NND * 33))[i] = make_int4(0, 0, 0, 0);
}

// Stage 1 (per graph): agg1[dst] += x[src]. ILP-4.
__global__ void __launch_bounds__(256) edge1_kernel(
        const float* __restrict__ x, const void* __restrict__ ep, int g) {
    long long tid = (long long)blockIdx.x * blockDim.x + threadIdx.x;
    const long long NT = (long long)NE / 4;
    if (tid >= NT) return;
    bool is64 = detect_int64(ep, 2LL * NE, (unsigned long long)NND);
    long long e = tid * 4;

    int s[4], d[4];
    load_edge4(ep, is64, e, s, d);
    float xv[4];
#pragma unroll
    for (int u = 0; u < 4; u++) xv[u] = __ldg(&x[s[u]]);
    float* aggb = g_agg1 + g * NND;
#pragma unroll
    for (int u = 0; u < 4; u++) atomicAdd(&aggb[d[u]], xv[u]);
}

// (per graph) t = x + agg1; bucket j = #(sorted th <= t); pack P.
__global__ void node_t_kernel(const float* __restrict__ x, int g) {
    __shared__ float th_s[32 * 32];
    for (int i = threadIdx.x; i < 32 * 32; i += blockDim.x) th_s[i] = g_th[i >> 5];
    __syncthreads();

    int i = blockIdx.x * blockDim.x + threadIdx.x;
    if (i >= NND) return;
    float t = x[i] + g_agg1[g * NND + i];

    int lane = threadIdx.x & 31;
    int j = 0;
#pragma unroll
    for (int st = 16; st >= 1; st >>= 1) {
        int c = j + st;
        if (th_s[((c - 1) << 5) | lane] <= t) j = c;
    }
    if (j == 31 && th_s[(31 << 5) | lane] <= t) j = 32;

    int q = __float2int_rn(t * 1024.f);
    int A = (1 << 24) + (1 << 17) + q;
    g_t[g * NND + i] = t;
    g_P[g * NND + i] = (j << 25) | A;
}

// Stage 2 (per graph): one RED.32 per edge: bkt[dst*33 + j] += A. ILP-4.
__global__ void __launch_bounds__(256) edgeb_kernel(const void* __restrict__ ep, int g) {
    long long tid = (long long)blockIdx.x * blockDim.x + threadIdx.x;
    const long long NT = (long long)NE / 4;
    if (tid >= NT) return;
    bool is64 = detect_int64(ep, 2LL * NE, (unsigned long long)NND);
    long long e = tid * 4;

    int s[4], d[4];
    load_edge4(ep, is64, e, s, d);
    const int* Pb = g_P + g * NND;
    int P[4];
#pragma unroll
    for (int u = 0; u < 4; u++) P[u] = __ldg(&Pb[s[u]]);

    int* bktb = g_bkt + (long long)g * NND * 33;
#pragma unroll
    for (int u = 0; u < 4; u++) {
        int j = P[u] >> 25;
        int A = P[u] & 0x01FFFFFF;
        atomicAdd(&bktb[d[u] * 33 + j], A);
    }
}

// Stage 3 (per graph): decode buckets, layer2, pool (signed). Warp per 4 nodes
// (2 pairs), 2-node interleaved chains, W2 in shared.
__global__ void __launch_bounds__(256) node_out_kernel(
        const void* __restrict__ bp,
        const float* __restrict__ W1, const float* __restrict__ b1,
        const float* __restrict__ W2, const float* __restrict__ b2,
        int g, float sign) {
    __shared__ float W2s[NH][NH];
    for (int i = threadIdx.x; i < NH * NH; i += blockDim.x)
        W2s[i >> 5][i & 31] = W2[i];
    __syncthreads();

    const int CH = 4;
    const int chunks = NND / CH;  // 25000
    int lane = threadIdx.x & 31;
    int warp = (blockIdx.x * blockDim.x + threadIdx.x) >> 5;
    if (warp >= chunks) return;
    int start = warp * CH;

    bool is64 = detect_int64(bp, (long long)NND, (unsigned long long)NG);
    float w1  = W1[lane];
    float bb1 = b1[lane];
    float bb2 = b2[lane];
    int   rnk = g_rank[lane];

    const float* tb = g_t + g * NND;
    float poolacc = 0.f;
    int curg = -1;

    for (int n = start; n < start + CH; n += 2) {
        const int* bktA = &g_bkt[((long long)(g * NND + n)) * 33];
        int VA = bktA[1 + lane], VA0 = bktA[0];
        int VB = bktA[33 + 1 + lane], VB0 = bktA[33];
        float tA = tb[n], tBv = tb[n + 1];

        float ccA = (float)(VA >> 24);
        float ssA = (float)((VA & 0xFFFFFF) - ((VA >> 24) << 17)) * (1.f / 1024.f);
        float ccB = (float)(VB >> 24);
        float ssB = (float)((VB & 0xFFFFFF) - ((VB >> 24) << 17)) * (1.f / 1024.f);
#pragma unroll
        for (int off = 1; off < 32; off <<= 1) {   // interleaved suffix scans
            float a1 = __shfl_down_sync(FULL, ssA, off);
            float a2 = __shfl_down_sync(FULL, ccA, off);
            float b1_ = __shfl_down_sync(FULL, ssB, off);
            float b2_ = __shfl_down_sync(FULL, ccB, off);
            if (lane + off < 32) { ssA += a1; ccA += a2; ssB += b1_; ccB += b2_; }
        }
        float c0A = (float)(VA0 >> 24);
        float s0A = (float)((VA0 & 0xFFFFFF) - ((VA0 >> 24) << 17)) * (1.f / 1024.f);
        float c0B = (float)(VB0 >> 24);
        float s0B = (float)((VB0 & 0xFFFFFF) - ((VB0 >> 24) << 17)) * (1.f / 1024.f);
        float TSA = s0A + __shfl_sync(FULL, ssA, 0);
        float TCA = c0A + __shfl_sync(FULL, ccA, 0);
        float TSB = s0B + __shfl_sync(FULL, ssB, 0);
        float TCB = c0B + __shfl_sync(FULL, ccB, 0);
        float mSA = __shfl_sync(FULL, ssA, rnk);
        float mCA = __shfl_sync(FULL, ccA, rnk);
        float mSB = __shfl_sync(FULL, ssB, rnk);
        float mCB = __shfl_sync(FULL, ccB, rnk);

        float aggA, aggB;
        if (w1 > 0.f) {
            aggA = w1 * mSA + bb1 * mCA;
            aggB = w1 * mSB + bb1 * mCB;
        } else if (w1 < 0.f) {
            aggA = w1 * (TSA - mSA) + bb1 * (TCA - mCA);
            aggB = w1 * (TSB - mSB) + bb1 * (TCB - mCB);
        } else {
            aggA = fmaxf(bb1, 0.f) * TCA;
            aggB = fmaxf(bb1, 0.f) * TCB;
        }

        float vA = fmaxf(fmaf(tA,  w1, bb1), 0.f) + aggA;
        float vB = fmaxf(fmaf(tBv, w1, bb1), 0.f) + aggB;

        float accA = bb2, accA2 = 0.f, accB = bb2, accB2 = 0.f;
#pragma unroll
        for (int k = 0; k < 32; k += 2) {
            float w2a = W2s[k][lane], w2b = W2s[k + 1][lane];
            accA  = fmaf(__shfl_sync(FULL, vA, k),     w2a, accA);
            accA2 = fmaf(__shfl_sync(FULL, vA, k + 1), w2b, accA2);
            accB  = fmaf(__shfl_sync(FULL, vB, k),     w2a, accB);
            accB2 = fmaf(__shfl_sync(FULL, vB, k + 1), w2b, accB2);
        }
        float oA = fmaxf(accA + accA2, 0.f);
        float oB = fmaxf(accB + accB2, 0.f);

        int bgA = is64 ? (int)((const long long*)bp)[n]
                       : ((const int*)bp)[n];
        int bgB = is64 ? (int)((const long long*)bp)[n + 1]
                       : ((const int*)bp)[n + 1];
        if (bgA != curg) {
            if (curg >= 0) atomicAdd(&g_pool[curg * NH + lane], sign * poolacc);
            poolacc = 0.f;
            curg = bgA;
        }
        poolacc += oA;
        if (bgB != curg) {
            atomicAdd(&g_pool[curg * NH + lane], sign * poolacc);
            poolacc = 0.f;
            curg = bgB;
        }
        poolacc += oB;
    }
    if (curg >= 0) atomicAdd(&g_pool[curg * NH + lane], sign * poolacc);
}

__global__ void abs_kernel(float* __restrict__ out) {
    int i = blockIdx.x * blockDim.x + threadIdx.x;
    if (i < NG * NH) out[i] = fabsf(g_pool[i]);
}

// ---------------- launch: LOCKSTEP 2-stream pipeline (no stagger) ----------------
// Both per-graph chains run simultaneously; edge kernels share the LTS floor
// (same total as a combined kernel) while node stages mutually overlap.
extern "C" void kernel_launch(void* const* d_in, const int* in_sizes, int n_in,
                              void* d_out, int out_size) {
    const float* x1  = (const float*)d_in[0];
    const void*  ei1 = d_in[1];
    const void*  bt1 = d_in[2];
    const float* x2  = (const float*)d_in[3];
    const void*  ei2 = d_in[4];
    const void*  bt2 = d_in[5];
    const float* W1  = (const float*)d_in[6];
    const float* b1  = (const float*)d_in[7];
    const float* W2  = (const float*)d_in[8];
    const float* b2  = (const float*)d_in[9];
    float* out = (float*)d_out;

    static cudaStream_t s2 = nullptr;
    static cudaEvent_t ev0 = nullptr, ev2 = nullptr;
    if (!s2) {
        cudaStreamCreateWithFlags(&s2, cudaStreamNonBlocking);
        cudaEventCreateWithFlags(&ev0, cudaEventDisableTiming);
        cudaEventCreateWithFlags(&ev2, cudaEventDisableTiming);
    }

    const int EB = (int)(((long long)NE / 4 + 255) / 256);        // edge blocks / graph
    const int NB = (NND + 255) / 256;                             // node_t blocks / graph
    const int OB = ((NND / 4) * 32 + 255) / 256;                  // node_out blocks / graph
    const int ZB = (int)(((long long)NND * 33 / 4 + 255) / 256);  // zbkt blocks / graph

    // head: tiny zero + prep on main, then fork
    zeroA_kernel<<<(2 * NND / 4 + 255) / 256, 256>>>(W1, b1);
    cudaEventRecord(ev0, 0);

    // s2: graph-2 chain (lockstep with main)
    cudaStreamWaitEvent(s2, ev0, 0);
    zbkt_kernel<<<ZB, 256, 0, s2>>>(1);
    edge1_kernel<<<EB, 256, 0, s2>>>(x2, ei2, 1);
    node_t_kernel<<<NB, 256, 0, s2>>>(x2, 1);
    edgeb_kernel<<<EB, 256, 0, s2>>>(ei2, 1);
    node_out_kernel<<<OB, 256, 0, s2>>>(bt2, W1, b1, W2, b2, 1, -1.f);
    cudaEventRecord(ev2, s2);

    // main: graph-1 chain (runs concurrently with s2)
    zbkt_kernel<<<ZB, 256>>>(0);
    edge1_kernel<<<EB, 256>>>(x1, ei1, 0);
    node_t_kernel<<<NB, 256>>>(x1, 0);
    edgeb_kernel<<<EB, 256>>>(ei1, 0);
    node_out_kernel<<<OB, 256>>>(bt1, W1, b1, W2, b2, 0, 1.f);

    // join and finalize
    cudaStreamWaitEvent(0, ev2, 0);
    abs_kernel<<<(NG * NH + 255) / 256, 256>>>(out);
}

// round 16
// speedup vs baseline: 1.0904x; 1.0002x over previous
#include <cuda_runtime.h>
#include <cstdint>
#include <math_constants.h>

#define NND 100000
#define NE  3200000
#define NG  128
#define NH  32
#define FULL 0xffffffffu

// ---------------- device scratch (allocation-free) ----------------
__device__ __align__(16) float g_agg1[2 * NND];          // 0.8 MB
__device__ __align__(16) float g_t   [2 * NND];          // 0.8 MB
__device__ __align__(16) int   g_P   [2 * NND];          // 0.8 MB   packed (j<<25)|A
__device__ __align__(16) int   g_bkt [2LL * NND * 33];   // 26.4 MB  packed count/sum
__device__ __align__(16) float g_pool[NG * NH];          // 16 KB (signed: g1 +, g2 -)
__device__ float g_th[NH];     // sorted thresholds
__device__ int   g_rank[NH];   // rank of threshold k

// ---------------- int64 vs int32 index detection ----------------
__device__ __forceinline__ bool detect_int64(const void* p, long long nelem,
                                             unsigned long long maxval) {
    const long long* q = (const long long*)p;
    long long a = q[nelem / 2 - 1];
    long long b = q[nelem / 2 - 2];
    return ((unsigned long long)a < maxval) && ((unsigned long long)b < maxval);
}

// Load 4 consecutive edges (e % 4 == 0) with wide loads.
__device__ __forceinline__ void load_edge4(const void* ep, bool is64, long long e,
                                           int (&src)[4], int (&dst)[4]) {
    if (is64) {
        const longlong2* q = (const longlong2*)ep;
        longlong2 s0 = q[e >> 1], s1 = q[(e >> 1) + 1];
        longlong2 d0 = q[((long long)NE + e) >> 1], d1 = q[(((long long)NE + e) >> 1) + 1];
        src[0] = (int)s0.x; src[1] = (int)s0.y; src[2] = (int)s1.x; src[3] = (int)s1.y;
        dst[0] = (int)d0.x; dst[1] = (int)d0.y; dst[2] = (int)d1.x; dst[3] = (int)d1.y;
    } else {
        const int* qi = (const int*)ep;
        int4 s = ((const int4*)qi)[e >> 2];
        int4 d = ((const int4*)(qi + NE))[e >> 2];
        src[0] = s.x; src[1] = s.y; src[2] = s.z; src[3] = s.w;
        dst[0] = d.x; dst[1] = d.y; dst[2] = d.z; dst[3] = d.w;
    }
}

// ---------------- kernels ----------------

// Tiny head zero: agg1 (both) + pool + threshold sort.
__global__ void zeroA_kernel(const float* __restrict__ W1,
                             const float* __restrict__ b1) {
    int i = blockIdx.x * blockDim.x + threadIdx.x;
    float4 zf = make_float4(0.f, 0.f, 0.f, 0.f);
    if (i < 2 * NND / 4)  ((float4*)g_agg1)[i] = zf;
    if (i < NG * NH / 4)  ((float4*)g_pool)[i] = zf;

    if (blockIdx.x == 0 && threadIdx.x < 32) {
        int lane = threadIdx.x;
        float w = W1[lane], b = b1[lane];
        float th = (w != 0.f) ? (-b / w) : CUDART_INF_F;
        int r = 0;
#pragma unroll
        for (int k = 0; k < NH; k++) {
            float o = __shfl_sync(FULL, th, k);
            r += (o < th) || (o == th && k < lane);
        }
        g_th[r] = th;
        g_rank[lane] = r;
    }
}

#define ZB4 ((int)((long long)NND * 33 / 4))   // 825000 int4 stores per graph

// Stage 1 (per graph), FUSED with bucket zeroing:
//   blocks [0, ZB): zero this graph's 13.2MB bucket region (coalesced int4)
//   blocks [ZB, ..): agg1[dst] += x[src], ILP-4
// The two halves touch disjoint state; no intra-kernel ordering needed.
__global__ void __launch_bounds__(256) edge1z_kernel(
        const float* __restrict__ x, const void* __restrict__ ep, int g, int ZB) {
    if (blockIdx.x < (unsigned)ZB) {
        long long i = (long long)blockIdx.x * blockDim.x + threadIdx.x;
        if (i < ZB4)
            ((int4*)(g_bkt + (long long)g * NND * 33))[i] = make_int4(0, 0, 0, 0);
        return;
    }
    long long tid = (long long)(blockIdx.x - ZB) * blockDim.x + threadIdx.x;
    const long long NT = (long long)NE / 4;
    if (tid >= NT) return;
    bool is64 = detect_int64(ep, 2LL * NE, (unsigned long long)NND);
    long long e = tid * 4;

    int s[4], d[4];
    load_edge4(ep, is64, e, s, d);
    float xv[4];
#pragma unroll
    for (int u = 0; u < 4; u++) xv[u] = __ldg(&x[s[u]]);
    float* aggb = g_agg1 + g * NND;
#pragma unroll
    for (int u = 0; u < 4; u++) atomicAdd(&aggb[d[u]], xv[u]);
}

// (per graph) t = x + agg1; bucket j = #(sorted th <= t); pack P.
__global__ void node_t_kernel(const float* __restrict__ x, int g) {
    __shared__ float th_s[32 * 32];
    for (int i = threadIdx.x; i < 32 * 32; i += blockDim.x) th_s[i] = g_th[i >> 5];
    __syncthreads();

    int i = blockIdx.x * blockDim.x + threadIdx.x;
    if (i >= NND) return;
    float t = x[i] + g_agg1[g * NND + i];

    int lane = threadIdx.x & 31;
    int j = 0;
#pragma unroll
    for (int st = 16; st >= 1; st >>= 1) {
        int c = j + st;
        if (th_s[((c - 1) << 5) | lane] <= t) j = c;
    }
    if (j == 31 && th_s[(31 << 5) | lane] <= t) j = 32;

    int q = __float2int_rn(t * 1024.f);
    int A = (1 << 24) + (1 << 17) + q;
    g_t[g * NND + i] = t;
    g_P[g * NND + i] = (j << 25) | A;
}

// Stage 2 (per graph): one RED.32 per edge: bkt[dst*33 + j] += A. ILP-4.
__global__ void __launch_bounds__(256) edgeb_kernel(const void* __restrict__ ep, int g) {
    long long tid = (long long)blockIdx.x * blockDim.x + threadIdx.x;
    const long long NT = (long long)NE / 4;
    if (tid >= NT) return;
    bool is64 = detect_int64(ep, 2LL * NE, (unsigned long long)NND);
    long long e = tid * 4;

    int s[4], d[4];
    load_edge4(ep, is64, e, s, d);
    const int* Pb = g_P + g * NND;
    int P[4];
#pragma unroll
    for (int u = 0; u < 4; u++) P[u] = __ldg(&Pb[s[u]]);

    int* bktb = g_bkt + (long long)g * NND * 33;
#pragma unroll
    for (int u = 0; u < 4; u++) {
        int j = P[u] >> 25;
        int A = P[u] & 0x01FFFFFF;
        atomicAdd(&bktb[d[u] * 33 + j], A);
    }
}

// Stage 3 (per graph): decode buckets, layer2, pool (signed). Warp per 4 nodes
// (2 pairs), 2-node interleaved chains, W2 in shared.
__global__ void __launch_bounds__(256) node_out_kernel(
        const void* __restrict__ bp,
        const float* __restrict__ W1, const float* __restrict__ b1,
        const float* __restrict__ W2, const float* __restrict__ b2,
        int g, float sign) {
    __shared__ float W2s[NH][NH];
    for (int i = threadIdx.x; i < NH * NH; i += blockDim.x)
        W2s[i >> 5][i & 31] = W2[i];
    __syncthreads();

    const int CH = 4;
    const int chunks = NND / CH;  // 25000
    int lane = threadIdx.x & 31;
    int warp = (blockIdx.x * blockDim.x + threadIdx.x) >> 5;
    if (warp >= chunks) return;
    int start = warp * CH;

    bool is64 = detect_int64(bp, (long long)NND, (unsigned long long)NG);
    float w1  = W1[lane];
    float bb1 = b1[lane];
    float bb2 = b2[lane];
    int   rnk = g_rank[lane];

    const float* tb = g_t + g * NND;
    float poolacc = 0.f;
    int curg = -1;

    for (int n = start; n < start + CH; n += 2) {
        const int* bktA = &g_bkt[((long long)(g * NND + n)) * 33];
        int VA = bktA[1 + lane], VA0 = bktA[0];
        int VB = bktA[33 + 1 + lane], VB0 = bktA[33];
        float tA = tb[n], tBv = tb[n + 1];

        float ccA = (float)(VA >> 24);
        float ssA = (float)((VA & 0xFFFFFF) - ((VA >> 24) << 17)) * (1.f / 1024.f);
        float ccB = (float)(VB >> 24);
        float ssB = (float)((VB & 0xFFFFFF) - ((VB >> 24) << 17)) * (1.f / 1024.f);
#pragma unroll
        for (int off = 1; off < 32; off <<= 1) {   // interleaved suffix scans
            float a1 = __shfl_down_sync(FULL, ssA, off);
            float a2 = __shfl_down_sync(FULL, ccA, off);
            float b1_ = __shfl_down_sync(FULL, ssB, off);
            float b2_ = __shfl_down_sync(FULL, ccB, off);
            if (lane + off < 32) { ssA += a1; ccA += a2; ssB += b1_; ccB += b2_; }
        }
        float c0A = (float)(VA0 >> 24);
        float s0A = (float)((VA0 & 0xFFFFFF) - ((VA0 >> 24) << 17)) * (1.f / 1024.f);
        float c0B = (float)(VB0 >> 24);
        float s0B = (float)((VB0 & 0xFFFFFF) - ((VB0 >> 24) << 17)) * (1.f / 1024.f);
        float TSA = s0A + __shfl_sync(FULL, ssA, 0);
        float TCA = c0A + __shfl_sync(FULL, ccA, 0);
        float TSB = s0B + __shfl_sync(FULL, ssB, 0);
        float TCB = c0B + __shfl_sync(FULL, ccB, 0);
        float mSA = __shfl_sync(FULL, ssA, rnk);
        float mCA = __shfl_sync(FULL, ccA, rnk);
        float mSB = __shfl_sync(FULL, ssB, rnk);
        float mCB = __shfl_sync(FULL, ccB, rnk);

        float aggA, aggB;
        if (w1 > 0.f) {
            aggA = w1 * mSA + bb1 * mCA;
            aggB = w1 * mSB + bb1 * mCB;
        } else if (w1 < 0.f) {
            aggA = w1 * (TSA - mSA) + bb1 * (TCA - mCA);
            aggB = w1 * (TSB - mSB) + bb1 * (TCB - mCB);
        } else {
            aggA = fmaxf(bb1, 0.f) * TCA;
            aggB = fmaxf(bb1, 0.f) * TCB;
        }

        float vA = fmaxf(fmaf(tA,  w1, bb1), 0.f) + aggA;
        float vB = fmaxf(fmaf(tBv, w1, bb1), 0.f) + aggB;

        float accA = bb2, accA2 = 0.f, accB = bb2, accB2 = 0.f;
#pragma unroll
        for (int k = 0; k < 32; k += 2) {
            float w2a = W2s[k][lane], w2b = W2s[k + 1][lane];
            accA  = fmaf(__shfl_sync(FULL, vA, k),     w2a, accA);
            accA2 = fmaf(__shfl_sync(FULL, vA, k + 1), w2b, accA2);
            accB  = fmaf(__shfl_sync(FULL, vB, k),     w2a, accB);
            accB2 = fmaf(__shfl_sync(FULL, vB, k + 1), w2b, accB2);
        }
        float oA = fmaxf(accA + accA2, 0.f);
        float oB = fmaxf(accB + accB2, 0.f);

        int bgA = is64 ? (int)((const long long*)bp)[n]
                       : ((const int*)bp)[n];
        int bgB = is64 ? (int)((const long long*)bp)[n + 1]
                       : ((const int*)bp)[n + 1];
        if (bgA != curg) {
            if (curg >= 0) atomicAdd(&g_pool[curg * NH + lane], sign * poolacc);
            poolacc = 0.f;
            curg = bgA;
        }
        poolacc += oA;
        if (bgB != curg) {
            atomicAdd(&g_pool[curg * NH + lane], sign * poolacc);
            poolacc = 0.f;
            curg = bgB;
        }
        poolacc += oB;
    }
    if (curg >= 0) atomicAdd(&g_pool[curg * NH + lane], sign * poolacc);
}

__global__ void abs_kernel(float* __restrict__ out) {
    int i = blockIdx.x * blockDim.x + threadIdx.x;
    if (i < NG * NH) out[i] = fabsf(g_pool[i]);
}

// ---------------- launch: LOCKSTEP 2-stream pipeline, zbkt fused into edge1 ----
extern "C" void kernel_launch(void* const* d_in, const int* in_sizes, int n_in,
                              void* d_out, int out_size) {
    const float* x1  = (const float*)d_in[0];
    const void*  ei1 = d_in[1];
    const void*  bt1 = d_in[2];
    const float* x2  = (const float*)d_in[3];
    const void*  ei2 = d_in[4];
    const void*  bt2 = d_in[5];
    const float* W1  = (const float*)d_in[6];
    const float* b1  = (const float*)d_in[7];
    const float* W2  = (const float*)d_in[8];
    const float* b2  = (const float*)d_in[9];
    float* out = (float*)d_out;

    static cudaStream_t s2 = nullptr;
    static cudaEvent_t ev0 = nullptr, ev2 = nullptr;
    if (!s2) {
        cudaStreamCreateWithFlags(&s2, cudaStreamNonBlocking);
        cudaEventCreateWithFlags(&ev0, cudaEventDisableTiming);
        cudaEventCreateWithFlags(&ev2, cudaEventDisableTiming);
    }

    const int EB = (int)(((long long)NE / 4 + 255) / 256);        // edge blocks / graph
    const int NB = (NND + 255) / 256;                             // node_t blocks / graph
    const int OB = ((NND / 4) * 32 + 255) / 256;                  // node_out blocks / graph
    const int ZB = (ZB4 + 255) / 256;                             // zero blocks / graph

    // head: tiny zero + prep on main, then fork
    zeroA_kernel<<<(2 * NND / 4 + 255) / 256, 256>>>(W1, b1);
    cudaEventRecord(ev0, 0);

    // s2: graph-2 chain (lockstep with main)
    cudaStreamWaitEvent(s2, ev0, 0);
    edge1z_kernel<<<ZB + EB, 256, 0, s2>>>(x2, ei2, 1, ZB);
    node_t_kernel<<<NB, 256, 0, s2>>>(x2, 1);
    edgeb_kernel<<<EB, 256, 0, s2>>>(ei2, 1);
    node_out_kernel<<<OB, 256, 0, s2>>>(bt2, W1, b1, W2, b2, 1, -1.f);
    cudaEventRecord(ev2, s2);

    // main: graph-1 chain (runs concurrently with s2)
    edge1z_kernel<<<ZB + EB, 256>>>(x1, ei1, 0, ZB);
    node_t_kernel<<<NB, 256>>>(x1, 0);
    edgeb_kernel<<<EB, 256>>>(ei1, 0);
    node_out_kernel<<<OB, 256>>>(bt1, W1, b1, W2, b2, 0, 1.f);

    // join and finalize
    cudaStreamWaitEvent(0, ev2, 0);
    abs_kernel<<<(NG * NH + 255) / 256, 256>>>(out);
}